// round 8
// baseline (speedup 1.0000x reference)
#include <cuda_runtime.h>

#define SLEN 64
#define BATCH 64
#define EDIM 256
#define G4 2048
#define OUTV 6000
#define DSTEPS 63
#define NCTA 128
#define TPB 256
#define PART (G4 * 64)   // 131072 floats: one step's transposed gate-input slab

typedef unsigned long long u64;

// ---------------- static device scratch ----------------
__device__ float g_XencT[SLEN * PART];     // [st][gcol][b]
__device__ float g_XdecT[DSTEPS * PART];   // [st][gcol][b]
__device__ float g_embS[SLEN * BATCH * EDIM];
__device__ float g_embT[DSTEPS * BATCH * EDIM];
__device__ float g_encouts[SLEN * BATCH * 512];  // [st][b][j]  (b-major)
__device__ float g_dech1[DSTEPS * BATCH * 512];  // [st][b][j]
__device__ float g_W0T[512 * 2048];     // eWhh0 transposed [k][gcol]
__device__ float g_W1T[1024 * 2048];    // [eWih1 ; eWhh1] transposed
__device__ float g_D0T[1024 * 2048];    // [dWih0[:,256:768] ; dWhh0] transposed
__device__ float g_D1T[1024 * 2048];    // [dWih1 ; dWhh1] transposed
__device__ float g_S0[1024 * 64];       // state [h0|h1], feature-major [j][b]
__device__ float g_S1[1024 * 64];
__device__ float g_ctx[512 * 64];       // attention context, feature-major
__device__ float g_c0T[512 * 64];       // cell states, feature-major
__device__ float g_c1T[512 * 64];
__device__ unsigned g_bar_cnt;
__device__ unsigned g_bar_gen;

// ---------------- f32x2 helpers ----------------
static __device__ __forceinline__ u64 splat2(float x) {
    u64 r; asm("mov.b64 %0, {%1, %1};" : "=l"(r) : "f"(x)); return r;
}
static __device__ __forceinline__ u64 ffma2(u64 a, u64 b, u64 c) {
    u64 d; asm("fma.rn.f32x2 %0, %1, %2, %3;" : "=l"(d) : "l"(a), "l"(b), "l"(c)); return d;
}
static __device__ __forceinline__ float2 unpack2(u64 v) {
    float2 r; asm("mov.b64 {%0, %1}, %2;" : "=f"(r.x), "=f"(r.y) : "l"(v)); return r;
}
static __device__ __forceinline__ float sigmf(float x) {
    return 1.0f / (1.0f + __expf(-x));
}

// ---------------- grid barrier (R5 acq/rel atomic) ----------------
static __device__ __forceinline__ void gbar() {
    __syncthreads();
    if (threadIdx.x == 0) {
        unsigned gen;
        asm volatile("ld.acquire.gpu.u32 %0, [%1];" : "=r"(gen) : "l"(&g_bar_gen) : "memory");
        unsigned prev;
        asm volatile("atom.acq_rel.gpu.add.u32 %0, [%1], %2;"
                     : "=r"(prev) : "l"(&g_bar_cnt), "r"(1u) : "memory");
        if (prev == NCTA - 1) {
            asm volatile("st.relaxed.gpu.u32 [%0], %1;" :: "l"(&g_bar_cnt), "r"(0u) : "memory");
            asm volatile("st.release.gpu.u32 [%0], %1;" :: "l"(&g_bar_gen), "r"(gen + 1u) : "memory");
        } else {
            unsigned cur;
            do {
                asm volatile("ld.acquire.gpu.u32 %0, [%1];" : "=r"(cur) : "l"(&g_bar_gen) : "memory");
            } while (cur == gen);
        }
    }
    __syncthreads();
}

// ---------------- fused LSTM cell: full-K GEMM for 16 gate cols + local pointwise ----
// CTA handles j's j0..j0+3 (4 h-indices) = gate cols {g*512 + j0..j0+3}, g=0..3.
// G[b][col] = sum_k A[k][b] * WT[k][col];  A from A0 (k<512) / A1 (k>=512).
// Then: gates + bias (+xT) -> sigmoid/tanh -> c update -> h out.
template <int KLEN>
static __device__ __forceinline__ void cell(
    const float* __restrict__ A0, const float* __restrict__ A1,
    const float* __restrict__ WT, int j0,
    const float* __restrict__ xT,
    const float* __restrict__ bih, const float* __restrict__ bhh,
    float* __restrict__ cT, float* __restrict__ hOut, float* __restrict__ bmaj,
    float (*Ash)[64], float (*Wsh)[16], u64 (*Gshu)[16][32])
{
    const int tid = threadIdx.x;
    const int q = tid >> 6;          // K-quarter within each 64-chunk
    const int u = tid & 63;
    const int rg = u & 15;           // rows (batches) rg*4..rg*4+3
    const int gg = u >> 4;           // gate block 0..3
    u64 acc[2][4];
#pragma unroll
    for (int rp = 0; rp < 2; rp++)
#pragma unroll
        for (int c = 0; c < 4; c++) acc[rp][c] = 0ull;

    // loaders: Ash 64x64 (4 float4/thread), Wsh 64x16 (1 float4/thread)
    const int kra = tid >> 4, cba = (tid & 15) * 4;
    const int krw = tid >> 2, gw = tid & 3;
    float4 av[4], wv;
    {
        const float* Ab = A0;  // kb = 0 always < 512
#pragma unroll
        for (int h = 0; h < 4; h++)
            av[h] = __ldcg((const float4*)&Ab[(kra + h * 16) * 64 + cba]);
        wv = *(const float4*)&WT[(size_t)krw * 2048 + gw * 512 + j0];
    }
    for (int kb = 0; kb < KLEN; kb += 64) {
#pragma unroll
        for (int h = 0; h < 4; h++) *(float4*)&Ash[kra + h * 16][cba] = av[h];
        *(float4*)&Wsh[krw][gw * 4] = wv;
        __syncthreads();
        if (kb + 64 < KLEN) {
            int kn = kb + 64;
            const float* Ab = (kn < 512) ? (A0 + kn * 64) : (A1 + (kn - 512) * 64);
#pragma unroll
            for (int h = 0; h < 4; h++)
                av[h] = __ldcg((const float4*)&Ab[(kra + h * 16) * 64 + cba]);
            wv = *(const float4*)&WT[(size_t)(kn + krw) * 2048 + gw * 512 + j0];
        }
        const int kk0 = q * 16;
#pragma unroll
        for (int i = 0; i < 16; i++) {
            int kk = kk0 + i;
            const u64* ad = (const u64*)&Ash[kk][rg * 4];
            u64 a0 = ad[0], a1 = ad[1];
            float4 w = *(const float4*)&Wsh[kk][gg * 4];
            u64 w0 = splat2(w.x), w1 = splat2(w.y), w2 = splat2(w.z), w3 = splat2(w.w);
            acc[0][0] = ffma2(a0, w0, acc[0][0]); acc[0][1] = ffma2(a0, w1, acc[0][1]);
            acc[0][2] = ffma2(a0, w2, acc[0][2]); acc[0][3] = ffma2(a0, w3, acc[0][3]);
            acc[1][0] = ffma2(a1, w0, acc[1][0]); acc[1][1] = ffma2(a1, w1, acc[1][1]);
            acc[1][2] = ffma2(a1, w2, acc[1][2]); acc[1][3] = ffma2(a1, w3, acc[1][3]);
        }
        __syncthreads();
    }
    // write per-quarter partials: float view Gshu[q][col][row(b)]
#pragma unroll
    for (int rp = 0; rp < 2; rp++)
#pragma unroll
        for (int c = 0; c < 4; c++)
            Gshu[q][gg * 4 + c][rg * 2 + rp] = acc[rp][c];
    __syncthreads();
    // local pointwise: thread = (jj, b)
    {
        const int jj = tid >> 6, b = tid & 63;
        const float* Gf = (const float*)Gshu;  // [4][16][64]
        float g[4];
#pragma unroll
        for (int gi = 0; gi < 4; gi++) {
            int col = gi * 4 + jj;
            float v = bih[gi * 512 + j0 + jj] + bhh[gi * 512 + j0 + jj];
            if (xT) v += xT[(size_t)(gi * 512 + j0 + jj) * 64 + b];
#pragma unroll
            for (int qq = 0; qq < 4; qq++) v += Gf[(qq * 16 + col) * 64 + b];
            g[gi] = v;
        }
        int ci = (j0 + jj) * 64 + b;
        float ig = sigmf(g[0]), fg = sigmf(g[1]), tg = tanhf(g[2]), og = sigmf(g[3]);
        float cn = fg * cT[ci] + ig * tg;
        cT[ci] = cn;
        float h = og * tanhf(cn);
        hOut[ci] = h;
        if (bmaj) bmaj[b * 512 + j0 + jj] = h;
    }
    __syncthreads();
}

// ---------------- attention (CTA = batch row b); reads h1_prev from cur ----------------
static __device__ __forceinline__ void attention(int b, const float* __restrict__ cur,
                                                 float* hsh, float* ssh, float* ash) {
    int tid = threadIdx.x;
    for (int k = tid; k < 512; k += TPB) hsh[k] = __ldcg(&cur[(512 + k) * 64 + b]);
    __syncthreads();
    int w = tid >> 5, lane = tid & 31;
    for (int s = w; s < 64; s += 8) {
        const float* e = g_encouts + (size_t)s * 32768 + (size_t)b * 512;
        float d = 0.f;
#pragma unroll 4
        for (int k = lane; k < 512; k += 32) d += e[k] * hsh[k];
#pragma unroll
        for (int o = 16; o; o >>= 1) d += __shfl_down_sync(0xffffffffu, d, o);
        if (!lane) ssh[s] = d;
    }
    __syncthreads();
    if (tid < 32) {
        float s0 = ssh[tid], s1 = ssh[tid + 32];
        float m = fmaxf(s0, s1);
#pragma unroll
        for (int o = 16; o; o >>= 1) m = fmaxf(m, __shfl_xor_sync(0xffffffffu, m, o));
        float e0 = __expf(s0 - m), e1 = __expf(s1 - m);
        float sum = e0 + e1;
#pragma unroll
        for (int o = 16; o; o >>= 1) sum += __shfl_xor_sync(0xffffffffu, sum, o);
        float inv = 1.f / sum;
        ash[tid] = e0 * inv;
        ash[tid + 32] = e1 * inv;
    }
    __syncthreads();
    for (int j = tid; j < 512; j += TPB) {
        float acc = 0.f;
#pragma unroll 8
        for (int s = 0; s < 64; s++)
            acc += ash[s] * g_encouts[(size_t)s * 32768 + (size_t)b * 512 + j];
        g_ctx[j * 64 + b] = acc;
    }
    __syncthreads();
}

// ---------------- persistent recurrence kernel ----------------
__global__ void __launch_bounds__(TPB, 1) recurrent(
    const float* __restrict__ ebih0, const float* __restrict__ ebhh0,
    const float* __restrict__ ebih1, const float* __restrict__ ebhh1,
    const float* __restrict__ dbih0, const float* __restrict__ dbhh0,
    const float* __restrict__ dbih1, const float* __restrict__ dbhh1)
{
    __shared__ __align__(16) float Ash[64][64];
    __shared__ __align__(16) float Wsh[64][16];
    __shared__ __align__(16) u64 Gshu[4][16][32];
    __shared__ float hsh[512];
    __shared__ float ssh[64];
    __shared__ float ashm[64];
    const int bid = blockIdx.x;
    const int gid = bid * TPB + threadIdx.x;   // 0..32767

    // zero initial states (fresh each launch / graph replay)
    g_S0[gid] = 0.f;
    g_S0[gid + 32768] = 0.f;
    g_c0T[gid] = 0.f;
    g_c1T[gid] = 0.f;
    gbar();

    const int j0 = bid * 4;

    // ---- encoder ----
    for (int st = 0; st < SLEN; st++) {
        float* cur = (st & 1) ? g_S1 : g_S0;
        float* nxt = (st & 1) ? g_S0 : g_S1;
        cell<512>(cur, cur, g_W0T, j0, g_XencT + (size_t)st * PART, ebih0, ebhh0,
                  g_c0T, nxt, nullptr, Ash, Wsh, Gshu);
        gbar();
        cell<1024>(nxt, cur + 512 * 64, g_W1T, j0, nullptr, ebih1, ebhh1,
                   g_c1T, nxt + 512 * 64, g_encouts + (size_t)st * 32768, Ash, Wsh, Gshu);
        gbar();
    }

    // ---- decoder (state parity continues: dst step uses cur = S[dst&1]) ----
    for (int dst = 0; dst < DSTEPS; dst++) {
        float* cur = (dst & 1) ? g_S1 : g_S0;
        float* nxt = (dst & 1) ? g_S0 : g_S1;
        if (bid < 64) attention(bid, cur, hsh, ssh, ashm);
        gbar();
        cell<1024>(g_ctx, cur, g_D0T, j0, g_XdecT + (size_t)dst * PART, dbih0, dbhh0,
                   g_c0T, nxt, nullptr, Ash, Wsh, Gshu);
        gbar();
        cell<1024>(nxt, cur + 512 * 64, g_D1T, j0, nullptr, dbih1, dbhh1,
                   g_c1T, nxt + 512 * 64, g_dech1 + (size_t)dst * 32768, Ash, Wsh, Gshu);
        gbar();
    }
}

// ---------------- prologue / epilogue kernels ----------------
__global__ void zero_kernel(float* __restrict__ p, int n) {
    int i = blockIdx.x * blockDim.x + threadIdx.x;
    if (i < n) p[i] = 0.0f;
}

__global__ void transpose_all(
    const float* __restrict__ eWhh0, const float* __restrict__ eWih1, const float* __restrict__ eWhh1,
    const float* __restrict__ dWih0, const float* __restrict__ dWhh0,
    const float* __restrict__ dWih1, const float* __restrict__ dWhh1)
{
    __shared__ float tile[32][33];
    const float* src; int lds = 512, coloff = 0, dstk0 = 0; float* dst;
    switch (blockIdx.z) {
        case 0: src = eWhh0; dst = g_W0T; break;
        case 1: src = eWih1; dst = g_W1T; break;
        case 2: src = eWhh1; dst = g_W1T; dstk0 = 512; break;
        case 3: src = dWih0; dst = g_D0T; lds = 768; coloff = 256; break;
        case 4: src = dWhh0; dst = g_D0T; dstk0 = 512; break;
        case 5: src = dWih1; dst = g_D1T; break;
        default: src = dWhh1; dst = g_D1T; dstk0 = 512; break;
    }
    int rb = blockIdx.x * 32, kb = blockIdx.y * 32;
    int tx = threadIdx.x & 31, ty = threadIdx.x >> 5;
#pragma unroll
    for (int i = 0; i < 4; i++)
        tile[ty + i * 8][tx] = src[(size_t)(rb + ty + i * 8) * lds + coloff + kb + tx];
    __syncthreads();
#pragma unroll
    for (int i = 0; i < 4; i++)
        dst[(size_t)(dstk0 + kb + ty + i * 8) * 2048 + rb + tx] = tile[tx][ty + i * 8];
}

__global__ void gather_embed(const int* __restrict__ src, const int* __restrict__ trg,
                             const float* __restrict__ enc_emb, const float* __restrict__ dec_emb) {
    int row = blockIdx.x;
    int t4 = threadIdx.x;
    if (row < SLEN * BATCH) {
        int tok = src[row];
        reinterpret_cast<float4*>(g_embS + (size_t)row * EDIM)[t4] =
            reinterpret_cast<const float4*>(enc_emb + (size_t)tok * EDIM)[t4];
    } else {
        int r = row - SLEN * BATCH;
        int tok = trg[r];
        reinterpret_cast<float4*>(g_embT + (size_t)r * EDIM)[t4] =
            reinterpret_cast<const float4*>(dec_emb + (size_t)tok * EDIM)[t4];
    }
}

// ---------------- big GEMM core (f32x2). xpose=1 -> write XT[st][c][b] ----------------
static __device__ __forceinline__ void gemm_core(
    const float* __restrict__ A, int lda, const float* __restrict__ W, int ldw,
    const float* __restrict__ bias, float* __restrict__ C, int ldc,
    int M, int N, int K, int bx, int by, int xpose)
{
    __shared__ __align__(16) float Ash[16][132];
    __shared__ __align__(16) float Wsh[16][132];
    int row0 = by * 128, col0 = bx * 128;
    int tid = threadIdx.x;
    int tx = tid & 15, ty = tid >> 4;
    int lr = tid >> 2, lk4 = (tid & 3) * 4;
    u64 acc[4][8];
#pragma unroll
    for (int p = 0; p < 4; p++)
#pragma unroll
        for (int j = 0; j < 8; j++) acc[p][j] = 0ull;

    float4 avr[2], wvr[2];
#pragma unroll
    for (int h = 0; h < 2; h++) {
        int rr = lr + h * 64;
        int r = row0 + rr, c = col0 + rr;
        avr[h] = (r < M) ? *(const float4*)&A[(size_t)r * lda + lk4] : make_float4(0, 0, 0, 0);
        wvr[h] = (c < N) ? *(const float4*)&W[(size_t)c * ldw + lk4] : make_float4(0, 0, 0, 0);
    }
    for (int kb = 0; kb < K; kb += 16) {
#pragma unroll
        for (int h = 0; h < 2; h++) {
            int rr = lr + h * 64;
            Ash[lk4 + 0][rr] = avr[h].x; Ash[lk4 + 1][rr] = avr[h].y;
            Ash[lk4 + 2][rr] = avr[h].z; Ash[lk4 + 3][rr] = avr[h].w;
            Wsh[lk4 + 0][rr] = wvr[h].x; Wsh[lk4 + 1][rr] = wvr[h].y;
            Wsh[lk4 + 2][rr] = wvr[h].z; Wsh[lk4 + 3][rr] = wvr[h].w;
        }
        __syncthreads();
        if (kb + 16 < K) {
            int kn = kb + 16;
#pragma unroll
            for (int h = 0; h < 2; h++) {
                int rr = lr + h * 64;
                int r = row0 + rr, c = col0 + rr;
                avr[h] = (r < M) ? *(const float4*)&A[(size_t)r * lda + kn + lk4] : make_float4(0, 0, 0, 0);
                wvr[h] = (c < N) ? *(const float4*)&W[(size_t)c * ldw + kn + lk4] : make_float4(0, 0, 0, 0);
            }
        }
#pragma unroll
        for (int kk = 0; kk < 16; kk++) {
            const u64* ap = (const u64*)&Ash[kk][ty * 8];
            u64 a0 = ap[0], a1 = ap[1], a2 = ap[2], a3 = ap[3];
            float4 w0 = *(const float4*)&Wsh[kk][tx * 8];
            float4 w1 = *(const float4*)&Wsh[kk][tx * 8 + 4];
            u64 ws[8];
            ws[0] = splat2(w0.x); ws[1] = splat2(w0.y); ws[2] = splat2(w0.z); ws[3] = splat2(w0.w);
            ws[4] = splat2(w1.x); ws[5] = splat2(w1.y); ws[6] = splat2(w1.z); ws[7] = splat2(w1.w);
#pragma unroll
            for (int j = 0; j < 8; j++) {
                acc[0][j] = ffma2(a0, ws[j], acc[0][j]);
                acc[1][j] = ffma2(a1, ws[j], acc[1][j]);
                acc[2][j] = ffma2(a2, ws[j], acc[2][j]);
                acc[3][j] = ffma2(a3, ws[j], acc[3][j]);
            }
        }
        __syncthreads();
    }
#pragma unroll
    for (int p = 0; p < 4; p++) {
        float2 v[8];
#pragma unroll
        for (int j = 0; j < 8; j++) v[j] = unpack2(acc[p][j]);
        int r = row0 + ty * 8 + p * 2;   // even; r and r+1 share the same 64-block
        if (xpose) {
            if (r < M) {
                int st = r >> 6, b = r & 63;
#pragma unroll
                for (int j = 0; j < 8; j++) {
                    int c = col0 + tx * 8 + j;
                    *(float2*)&C[(size_t)st * PART + (size_t)c * 64 + b] = make_float2(v[j].x, v[j].y);
                }
            }
        } else {
            if (r < M) {
#pragma unroll
                for (int j = 0; j < 8; j++) {
                    int c = col0 + tx * 8 + j;
                    if (c < N) C[(size_t)r * ldc + c] = v[j].x + (bias ? bias[c] : 0.0f);
                }
            }
            if (r + 1 < M) {
#pragma unroll
                for (int j = 0; j < 8; j++) {
                    int c = col0 + tx * 8 + j;
                    if (c < N) C[(size_t)(r + 1) * ldc + c] = v[j].y + (bias ? bias[c] : 0.0f);
                }
            }
        }
    }
}

__global__ void __launch_bounds__(256) big_gemm(
    const float* __restrict__ A, int lda, const float* __restrict__ W, int ldw,
    const float* __restrict__ bias, float* __restrict__ C, int ldc,
    int M, int N, int K)
{
    gemm_core(A, lda, W, ldw, bias, C, ldc, M, N, K, blockIdx.x, blockIdx.y, 0);
}

// fused input projections; writes transposed X slabs
__global__ void __launch_bounds__(256) proj_gemm(
    const float* __restrict__ eWih0, const float* __restrict__ dWih0)
{
    if (blockIdx.z == 0)
        gemm_core(g_embS, EDIM, eWih0, EDIM, nullptr, g_XencT, 0,
                  SLEN * BATCH, G4, EDIM, blockIdx.x, blockIdx.y, 1);
    else
        gemm_core(g_embT, EDIM, dWih0, 768, nullptr, g_XdecT, 0,
                  DSTEPS * BATCH, G4, EDIM, blockIdx.x, blockIdx.y, 1);
}

// ---------------- host ----------------
extern "C" void kernel_launch(void* const* d_in, const int* in_sizes, int n_in,
                              void* d_out, int out_size) {
    const int* src = (const int*)d_in[0];
    const int* trg = (const int*)d_in[1];
    const float* enc_emb = (const float*)d_in[2];
    const float* eWih0 = (const float*)d_in[3];
    const float* eWhh0 = (const float*)d_in[4];
    const float* ebih0 = (const float*)d_in[5];
    const float* ebhh0 = (const float*)d_in[6];
    const float* eWih1 = (const float*)d_in[7];
    const float* eWhh1 = (const float*)d_in[8];
    const float* ebih1 = (const float*)d_in[9];
    const float* ebhh1 = (const float*)d_in[10];
    const float* dec_emb = (const float*)d_in[11];
    const float* dWih0 = (const float*)d_in[12];
    const float* dWhh0 = (const float*)d_in[13];
    const float* dbih0 = (const float*)d_in[14];
    const float* dbhh0 = (const float*)d_in[15];
    const float* dWih1 = (const float*)d_in[16];
    const float* dWhh1 = (const float*)d_in[17];
    const float* dbih1 = (const float*)d_in[18];
    const float* dbhh1 = (const float*)d_in[19];
    const float* fcW = (const float*)d_in[20];
    const float* fcb = (const float*)d_in[21];
    float* out = (float*)d_out;

    float* dech1;
    cudaGetSymbolAddress((void**)&dech1, g_dech1);

    zero_kernel<<<(BATCH * OUTV + 255) / 256, 256>>>(out, BATCH * OUTV);
    gather_embed<<<SLEN * BATCH + DSTEPS * BATCH, 64>>>(src, trg, enc_emb, dec_emb);
    transpose_all<<<dim3(64, 16, 7), 256>>>(eWhh0, eWih1, eWhh1, dWih0, dWhh0, dWih1, dWhh1);
    proj_gemm<<<dim3(16, 32, 2), 256>>>(eWih0, dWih0);
    recurrent<<<NCTA, TPB>>>(ebih0, ebhh0, ebih1, ebhh1, dbih0, dbhh0, dbih1, dbhh1);
    big_gemm<<<dim3(47, 32), 256>>>(dech1, 512, fcW, 512, fcb,
                                    out + (size_t)BATCH * OUTV, OUTV,
                                    DSTEPS * BATCH, OUTV, 512);
}